// round 1
// baseline (speedup 1.0000x reference)
#include <cuda_runtime.h>
#include <cuda_bf16.h>
#include <math.h>

// Problem constants
#define BATCH 8
#define SEQ   1024
#define HID   768
#define NHEAD 12
#define DHEAD 64
#define ROWS  (BATCH*SEQ)          // 8192
#define FF    (2*HID)              // 1536

// ---------------- scratch (device globals; no allocations allowed) ----------
__device__ float g_q  [ROWS*HID];
__device__ float g_k  [ROWS*HID];
__device__ float g_v  [ROWS*HID];
__device__ float g_ctx[ROWS*HID];
__device__ float g_x  [ROWS*HID];
__device__ float g_ff1[ROWS*FF];
__device__ float g_ff2[ROWS*HID];

// ---------------- generic 128x128x8 SGEMM body (8x8 per thread) -------------
template<bool RELU>
__device__ __forceinline__ void sgemm_body(const float* __restrict__ A,
                                           const float* __restrict__ W,
                                           const float* __restrict__ bias,
                                           float* __restrict__ C,
                                           int K, int N)
{
    __shared__ float As[8][128];
    __shared__ float Bs[8][128];

    const int tid  = threadIdx.x;
    const int m0   = blockIdx.y << 7;
    const int n0   = blockIdx.x << 7;
    const int arow = tid >> 1,  acol = (tid & 1) << 2;   // A tile 128x8
    const int brow = tid >> 5,  bcol = (tid & 31) << 2;  // B tile 8x128
    const int tm   = (tid >> 4) << 3;                    // 8 rows per thread
    const int tn   = (tid & 15) << 3;                    // 8 cols per thread

    float acc[8][8];
#pragma unroll
    for (int i = 0; i < 8; i++)
#pragma unroll
        for (int j = 0; j < 8; j++) acc[i][j] = 0.f;

    const float* Ap = A + (size_t)(m0 + arow) * K + acol;
    const float* Wp = W + (size_t)brow * N + n0 + bcol;

    for (int k0 = 0; k0 < K; k0 += 8) {
        float4 a4 = *(const float4*)(Ap + k0);
        float4 b4 = *(const float4*)(Wp + (size_t)k0 * N);
        __syncthreads();
        As[acol + 0][arow] = a4.x;
        As[acol + 1][arow] = a4.y;
        As[acol + 2][arow] = a4.z;
        As[acol + 3][arow] = a4.w;
        *(float4*)&Bs[brow][bcol] = b4;
        __syncthreads();
#pragma unroll
        for (int kk = 0; kk < 8; kk++) {
            float4 a0 = *(const float4*)&As[kk][tm];
            float4 a1 = *(const float4*)&As[kk][tm + 4];
            float4 b0 = *(const float4*)&Bs[kk][tn];
            float4 b1 = *(const float4*)&Bs[kk][tn + 4];
            float ar[8] = {a0.x,a0.y,a0.z,a0.w,a1.x,a1.y,a1.z,a1.w};
            float br[8] = {b0.x,b0.y,b0.z,b0.w,b1.x,b1.y,b1.z,b1.w};
#pragma unroll
            for (int i = 0; i < 8; i++)
#pragma unroll
                for (int j = 0; j < 8; j++)
                    acc[i][j] = fmaf(ar[i], br[j], acc[i][j]);
        }
    }

    float4 bi0 = *(const float4*)(bias + n0 + tn);
    float4 bi1 = *(const float4*)(bias + n0 + tn + 4);
    float bb[8] = {bi0.x,bi0.y,bi0.z,bi0.w,bi1.x,bi1.y,bi1.z,bi1.w};
#pragma unroll
    for (int i = 0; i < 8; i++) {
        float o[8];
#pragma unroll
        for (int j = 0; j < 8; j++) {
            float v = acc[i][j] + bb[j];
            o[j] = RELU ? fmaxf(v, 0.f) : v;
        }
        float* cp = C + (size_t)(m0 + tm + i) * N + n0 + tn;
        *(float4*)cp       = make_float4(o[0], o[1], o[2], o[3]);
        *(float4*)(cp + 4) = make_float4(o[4], o[5], o[6], o[7]);
    }
}

// fused QKV projection: blockIdx.z selects which projection
__global__ void __launch_bounds__(256)
qkv_kernel(const float* __restrict__ x1,
           const float* __restrict__ Wq, const float* __restrict__ bq,
           const float* __restrict__ Wk, const float* __restrict__ bk,
           const float* __restrict__ Wv, const float* __restrict__ bv)
{
    const float* W; const float* bb; float* out;
    if      (blockIdx.z == 0) { W = Wq; bb = bq; out = g_q; }
    else if (blockIdx.z == 1) { W = Wk; bb = bk; out = g_k; }
    else                      { W = Wv; bb = bv; out = g_v; }
    sgemm_body<false>(x1, W, bb, out, HID, HID);
}

__global__ void __launch_bounds__(256)
ff1_kernel(const float* __restrict__ W1, const float* __restrict__ b1)
{
    sgemm_body<true>(g_x, W1, b1, g_ff1, HID, FF);
}

__global__ void __launch_bounds__(256)
ff2_kernel(const float* __restrict__ W2, const float* __restrict__ b2)
{
    sgemm_body<false>(g_ff1, W2, b2, g_ff2, FF, HID);
}

// ---------------- flash attention with post-softmax mask --------------------
// block = (q-tile of 64 rows, head, batch); 256 threads.
// thread (tr,tc): rows 4*tr..+3 of the q tile, cols 4*tc..+3 of k/d tile.
#define AS 68   // padded smem row stride (floats)

__global__ void __launch_bounds__(256)
attn_kernel(const float* __restrict__ wm)
{
    extern __shared__ float sm[];
    float* qst = sm;               // [d][r] transposed, 64 x AS
    float* kst = sm + 64 * AS;     // [d][k] transposed
    float* vs  = sm + 2 * 64 * AS; // [k][d]
    float* sct = sm + 3 * 64 * AS; // [k][r]  probs transposed

    const int tid = threadIdx.x;
    const int qt = blockIdx.x, h = blockIdx.y, b = blockIdx.z;
    const int q0 = qt * 64;
    const int tr = tid >> 4, tc = tid & 15;

    // cooperative-load mapping for transposed q/k store (conflict-free STS)
    const int lr = tid & 63;            // gmem row within 64-tile
    const int ld = (tid >> 6) << 4;     // 16-wide d-chunk
    // cooperative-load mapping for v (row-major)
    const int vr = tid >> 2;
    const int vd = (tid & 3) << 4;

    // load q tile, pre-scaled by 1/sqrt(DHEAD)
    {
        const float* qg = g_q + ((size_t)(b * SEQ + q0 + lr)) * HID + h * DHEAD + ld;
#pragma unroll
        for (int u = 0; u < 4; u++) {
            float4 t = *(const float4*)(qg + 4 * u);
            int d = ld + 4 * u;
            qst[(d + 0) * AS + lr] = t.x * 0.125f;
            qst[(d + 1) * AS + lr] = t.y * 0.125f;
            qst[(d + 2) * AS + lr] = t.z * 0.125f;
            qst[(d + 3) * AS + lr] = t.w * 0.125f;
        }
    }

    float m[4], l[4], acc[4][4];
#pragma unroll
    for (int i = 0; i < 4; i++) {
        m[i] = -1e30f; l[i] = 0.f;
#pragma unroll
        for (int j = 0; j < 4; j++) acc[i][j] = 0.f;
    }

    for (int kt = 0; kt < 16; ++kt) {
        const int kb = kt * 64;
        // load k (transposed) and v tiles
        {
            const float* kg = g_k + ((size_t)(b * SEQ + kb + lr)) * HID + h * DHEAD + ld;
#pragma unroll
            for (int u = 0; u < 4; u++) {
                float4 t = *(const float4*)(kg + 4 * u);
                int d = ld + 4 * u;
                kst[(d + 0) * AS + lr] = t.x;
                kst[(d + 1) * AS + lr] = t.y;
                kst[(d + 2) * AS + lr] = t.z;
                kst[(d + 3) * AS + lr] = t.w;
            }
            const float* vg = g_v + ((size_t)(b * SEQ + kb + vr)) * HID + h * DHEAD + vd;
#pragma unroll
            for (int u = 0; u < 4; u++)
                *(float4*)(vs + vr * AS + vd + 4 * u) = *(const float4*)(vg + 4 * u);
        }
        __syncthreads();

        // scores: s[i][j] = (q_row_i . k_col_j) (q already scaled)
        float s[4][4];
#pragma unroll
        for (int i = 0; i < 4; i++)
#pragma unroll
            for (int j = 0; j < 4; j++) s[i][j] = 0.f;

#pragma unroll 8
        for (int d = 0; d < 64; ++d) {
            float4 qv = *(const float4*)(qst + d * AS + 4 * tr);
            float4 kv = *(const float4*)(kst + d * AS + 4 * tc);
            float qa[4] = {qv.x, qv.y, qv.z, qv.w};
            float ka[4] = {kv.x, kv.y, kv.z, kv.w};
#pragma unroll
            for (int i = 0; i < 4; i++)
#pragma unroll
                for (int j = 0; j < 4; j++)
                    s[i][j] = fmaf(qa[i], ka[j], s[i][j]);
        }

        // mask tile (post-softmax multiplicative mask)
        float mk[4][4];
#pragma unroll
        for (int i = 0; i < 4; i++) {
            float4 t = *(const float4*)(wm + ((size_t)b * SEQ + (q0 + 4 * tr + i)) * SEQ + kb + 4 * tc);
            mk[i][0] = t.x; mk[i][1] = t.y; mk[i][2] = t.z; mk[i][3] = t.w;
        }

        // online softmax update per row (denominator is UNmasked)
#pragma unroll
        for (int i = 0; i < 4; i++) {
            float mx = fmaxf(fmaxf(s[i][0], s[i][1]), fmaxf(s[i][2], s[i][3]));
#pragma unroll
            for (int o = 8; o; o >>= 1)
                mx = fmaxf(mx, __shfl_xor_sync(0xffffffffu, mx, o));
            float mn = fmaxf(m[i], mx);
            float f  = __expf(m[i] - mn);
            float e0 = __expf(s[i][0] - mn);
            float e1 = __expf(s[i][1] - mn);
            float e2 = __expf(s[i][2] - mn);
            float e3 = __expf(s[i][3] - mn);
            float ls = e0 + e1 + e2 + e3;
#pragma unroll
            for (int o = 8; o; o >>= 1)
                ls += __shfl_xor_sync(0xffffffffu, ls, o);
            l[i] = l[i] * f + ls;
            m[i] = mn;
#pragma unroll
            for (int j = 0; j < 4; j++) acc[i][j] *= f;
            s[i][0] = e0 * mk[i][0];
            s[i][1] = e1 * mk[i][1];
            s[i][2] = e2 * mk[i][2];
            s[i][3] = e3 * mk[i][3];
        }

        // write masked probs transposed: sct[k][r]
#pragma unroll
        for (int j = 0; j < 4; j++) {
            float4 col = make_float4(s[0][j], s[1][j], s[2][j], s[3][j]);
            *(float4*)(sct + (4 * tc + j) * AS + 4 * tr) = col;
        }
        __syncthreads();

        // acc += P^T-tile @ V-tile
#pragma unroll 8
        for (int kk = 0; kk < 64; ++kk) {
            float4 p = *(const float4*)(sct + kk * AS + 4 * tr);
            float4 v = *(const float4*)(vs  + kk * AS + 4 * tc);
            float pa[4] = {p.x, p.y, p.z, p.w};
            float va[4] = {v.x, v.y, v.z, v.w};
#pragma unroll
            for (int i = 0; i < 4; i++)
#pragma unroll
                for (int j = 0; j < 4; j++)
                    acc[i][j] = fmaf(pa[i], va[j], acc[i][j]);
        }
        __syncthreads();
    }

    // ctx = acc / l
#pragma unroll
    for (int i = 0; i < 4; i++) {
        float inv = 1.0f / l[i];
        float4 o = make_float4(acc[i][0] * inv, acc[i][1] * inv,
                               acc[i][2] * inv, acc[i][3] * inv);
        *(float4*)(g_ctx + ((size_t)(b * SEQ + q0 + 4 * tr + i)) * HID + h * DHEAD + 4 * tc) = o;
    }
}

// ---------------- fused residual-add + LayerNorm (two-pass) -----------------
__device__ __forceinline__ void addln_body(const float* __restrict__ A,
                                           const float* __restrict__ Bv,
                                           const float* __restrict__ g,
                                           const float* __restrict__ be,
                                           float* __restrict__ out)
{
    const int row = blockIdx.x;
    const int tid = threadIdx.x;
    __shared__ float red[8];
    __shared__ float s_mu, s_rs;

    float4 v4 = make_float4(0.f, 0.f, 0.f, 0.f);
    float ls = 0.f;
    if (tid < 192) {
        float4 av = ((const float4*)(A  + (size_t)row * HID))[tid];
        float4 bv = ((const float4*)(Bv + (size_t)row * HID))[tid];
        v4 = make_float4(av.x + bv.x, av.y + bv.y, av.z + bv.z, av.w + bv.w);
        ls = v4.x + v4.y + v4.z + v4.w;
    }
    int lane = tid & 31, wid = tid >> 5;
#pragma unroll
    for (int o = 16; o; o >>= 1) ls += __shfl_xor_sync(0xffffffffu, ls, o);
    if (lane == 0) red[wid] = ls;
    __syncthreads();
    if (tid == 0) {
        float t = 0.f;
#pragma unroll
        for (int i = 0; i < 8; i++) t += red[i];
        s_mu = t * (1.0f / HID);
    }
    __syncthreads();
    float mu = s_mu;

    float4 dx = make_float4(v4.x - mu, v4.y - mu, v4.z - mu, v4.w - mu);
    float lv = 0.f;
    if (tid < 192)
        lv = dx.x * dx.x + dx.y * dx.y + dx.z * dx.z + dx.w * dx.w;
#pragma unroll
    for (int o = 16; o; o >>= 1) lv += __shfl_xor_sync(0xffffffffu, lv, o);
    __syncthreads();
    if (lane == 0) red[wid] = lv;
    __syncthreads();
    if (tid == 0) {
        float t = 0.f;
#pragma unroll
        for (int i = 0; i < 8; i++) t += red[i];
        s_rs = rsqrtf(t * (1.0f / HID) + 1e-5f);
    }
    __syncthreads();
    float rs = s_rs;

    if (tid < 192) {
        float4 g4  = ((const float4*)g)[tid];
        float4 be4 = ((const float4*)be)[tid];
        float4 o = make_float4(dx.x * rs * g4.x + be4.x,
                               dx.y * rs * g4.y + be4.y,
                               dx.z * rs * g4.z + be4.z,
                               dx.w * rs * g4.w + be4.w);
        ((float4*)(out + (size_t)row * HID))[tid] = o;
    }
}

__global__ void __launch_bounds__(256)
ln1_kernel(const float* __restrict__ g, const float* __restrict__ be)
{
    addln_body(g_ctx, g_q, g, be, g_x);  // x = LN(ctx + q_mixed)
}

__global__ void __launch_bounds__(256)
ln2_kernel(const float* __restrict__ g, const float* __restrict__ be,
           float* __restrict__ out)
{
    addln_body(g_x, g_ff2, g, be, out);  // out = LN(x + ff)
}

// ---------------- launch --------------------------------------------------
extern "C" void kernel_launch(void* const* d_in, const int* in_sizes, int n_in,
                              void* d_out, int out_size)
{
    const float* x1  = (const float*)d_in[0];
    const float* wm  = (const float*)d_in[1];
    const float* Wq  = (const float*)d_in[2];
    const float* bq  = (const float*)d_in[3];
    const float* Wk  = (const float*)d_in[4];
    const float* bk  = (const float*)d_in[5];
    const float* Wv  = (const float*)d_in[6];
    const float* bv  = (const float*)d_in[7];
    const float* g1  = (const float*)d_in[8];
    const float* be1 = (const float*)d_in[9];
    const float* g2  = (const float*)d_in[10];
    const float* be2 = (const float*)d_in[11];
    const float* W1  = (const float*)d_in[12];
    const float* b1  = (const float*)d_in[13];
    const float* W2  = (const float*)d_in[14];
    const float* b2  = (const float*)d_in[15];
    float* out = (float*)d_out;

    const int ATTN_SMEM = 4 * 64 * AS * (int)sizeof(float);  // 69632 B
    cudaFuncSetAttribute(attn_kernel,
                         cudaFuncAttributeMaxDynamicSharedMemorySize, ATTN_SMEM);

    // 1. QKV projections (fused into one launch, z selects projection)
    qkv_kernel<<<dim3(HID / 128, ROWS / 128, 3), 256>>>(x1, Wq, bq, Wk, bk, Wv, bv);

    // 2. flash attention with post-softmax mask
    attn_kernel<<<dim3(SEQ / 64, NHEAD, BATCH), 256, ATTN_SMEM>>>(wm);

    // 3. x = LN(ctx + q_mixed)
    ln1_kernel<<<ROWS, 256>>>(g1, be1);

    // 4. ff1 = relu(x @ W1 + b1)
    ff1_kernel<<<dim3(FF / 128, ROWS / 128), 256>>>(W1, b1);

    // 5. ff2 = ff1 @ W2 + b2
    ff2_kernel<<<dim3(HID / 128, ROWS / 128), 256>>>(W2, b2);

    // 6. out = LN(x + ff2)
    ln2_kernel<<<ROWS, 256>>>(g2, be2, out);
}